// round 9
// baseline (speedup 1.0000x reference)
#include <cuda_runtime.h>

#define GH 64
#define GW 64
#define NOBJ 16
#define FEAT 256
#define BATCH 4
#define DECAY 0.95f

#define NROWS (BATCH * GH * GW * NOBJ)   // 262144
#define ROW_OUT (FEAT + 2)               // 258 floats = 1032 B

// ---------------- Main kernel: pure decayed reformat copy -----------------
// Warp = 2 consecutive rows (r0 = 2*warp is always EVEN -> its output row
// base is 16B-aligned -> STG.128; odd row uses 2x STG.64).
// No update logic at all: the 64 scatter rows are fixed up by smg_patch.
__global__ __launch_bounds__(256, 8)
void smg_copy(const float* __restrict__ grid_state,
              const float* __restrict__ grid_conf,
              const float* __restrict__ grid_temp,
              float* __restrict__ out)
{
    const int tid   = threadIdx.x;
    const int lane  = tid & 31;
    const int wglob = blockIdx.x * 8 + (tid >> 5);
    const int r0    = wglob * 2;                    // even row

    // Front-batched bulk loads: 4x LDG.128 (2 rows x 64 float4)
    const float4* gs = (const float4*)grid_state + (size_t)r0 * (FEAT / 4);
    float4 v[4];
    #pragma unroll
    for (int j = 0; j < 4; j++)
        v[j] = gs[lane + 32 * j];

    // Lanes 0/1: conf/temp for their row (2 independent loads, short chain)
    if (lane < 2) {
        const int row = r0 + lane;
        const float c  = grid_conf[row];
        const float tm = grid_temp[row];
        *(float2*)(out + (size_t)row * ROW_OUT + FEAT) =
            make_float2(c * DECAY, tm);
    }

    // Row 0 (even): 16B-aligned -> STG.128
    float4* o0 = (float4*)(out + (size_t)r0 * ROW_OUT);
    o0[lane]      = v[0];
    o0[lane + 32] = v[1];

    // Row 1 (odd): 8B-aligned only -> 2x STG.64 per float4
    float* o1 = out + (size_t)(r0 + 1) * ROW_OUT;
    #pragma unroll
    for (int j = 2; j < 4; j++) {
        const int q = lane + 32 * (j & 1);
        *(float2*)(o1 + 4 * q)     = make_float2(v[j].x, v[j].y);
        *(float2*)(o1 + 4 * q + 2) = make_float2(v[j].z, v[j].w);
    }
}

// ---------------- Patch kernel: fix up the 64 scattered rows ---------------
// One block per (b, obj). Recomputes the blended row from the UNMODIFIED
// inputs and overwrites the full output row (features + conf + temporal).
// Runs after smg_copy in stream order.
__global__ __launch_bounds__(64, 1)
void smg_patch(const float* __restrict__ grid_state,
               const float* __restrict__ grid_conf,
               const float* __restrict__ grid_temp,
               const float* __restrict__ obj_feat,
               const float* __restrict__ positions,
               const float* __restrict__ occl,
               float* __restrict__ out)
{
    const int bo = blockIdx.x;                   // 0..63
    const int b  = bo >> 4;
    const int o  = bo & (NOBJ - 1);
    const int t  = threadIdx.x;                  // 0..63 -> one float4 each

    const float px = positions[bo * 2 + 0];
    const float py = positions[bo * 2 + 1];
    const int gwt = (int)fminf(fmaxf(px * (float)(GW - 1), 0.0f), 63.0f);
    const int ght = (int)fminf(fmaxf(py * (float)(GH - 1), 0.0f), 63.0f);
    const int row = (((b * GH + ght) * GW) + gwt) * NOBJ + o;

    const bool vis = occl[bo] < 0.5f;
    const float a  = vis ? 0.8f : 0.3f;
    const float ia = 1.0f - a;

    const float4 g4 = ((const float4*)(grid_state + (size_t)row * FEAT))[t];
    const float4 f4 = ((const float4*)(obj_feat   + (size_t)bo  * FEAT))[t];
    float4 r;
    r.x = a * f4.x + ia * g4.x;
    r.y = a * f4.y + ia * g4.y;
    r.z = a * f4.z + ia * g4.z;
    r.w = a * f4.w + ia * g4.w;

    float* orow = out + (size_t)row * ROW_OUT;   // 8B-aligned always
    *(float2*)(orow + 4 * t)     = make_float2(r.x, r.y);
    *(float2*)(orow + 4 * t + 2) = make_float2(r.z, r.w);

    if (t == 0) {
        float c  = grid_conf[row];
        float tm = grid_temp[row];
        c  = vis ? fminf(1.0f, c * 0.9f + 0.5f) : c * DECAY;
        tm += vis ? 1.0f : 0.5f;
        *(float2*)(orow + FEAT) = make_float2(c * DECAY, tm);
    }
}

extern "C" void kernel_launch(void* const* d_in, const int* in_sizes, int n_in,
                              void* d_out, int out_size)
{
    const float* grid_state = (const float*)d_in[0];
    const float* grid_conf  = (const float*)d_in[1];
    const float* grid_temp  = (const float*)d_in[2];
    const float* obj_feat   = (const float*)d_in[3];
    const float* positions  = (const float*)d_in[4];
    const float* occl       = (const float*)d_in[5];
    float* out = (float*)d_out;

    smg_copy<<<NROWS / 16, 256>>>(grid_state, grid_conf, grid_temp, out);
    smg_patch<<<BATCH * NOBJ, 64>>>(grid_state, grid_conf, grid_temp,
                                    obj_feat, positions, occl, out);
}

// round 10
// speedup vs baseline: 1.0193x; 1.0193x over previous
#include <cuda_runtime.h>

#define GH 64
#define GW 64
#define NOBJ 16
#define FEAT 256
#define BATCH 4
#define DECAY 0.95f

#define NROWS (BATCH * GH * GW * NOBJ)   // 262144
#define ROW_OUT (FEAT + 2)               // 258 floats = 1032 B

// ---------------- Main kernel: pure decayed reformat copy -----------------
// Warp = 2 consecutive rows (r0 = 2*warp is EVEN -> 16B-aligned -> STG.128;
// odd row uses 2x STG.64). No update logic: the 64 scatter rows are fixed up
// by smg_patch, which is PDL-overlapped with this kernel.
__global__ __launch_bounds__(256, 8)
void smg_copy(const float* __restrict__ grid_state,
              const float* __restrict__ grid_conf,
              const float* __restrict__ grid_temp,
              float* __restrict__ out)
{
    const int tid   = threadIdx.x;
    const int lane  = tid & 31;
    const int wglob = blockIdx.x * 8 + (tid >> 5);
    const int r0    = wglob * 2;                    // even row

    // Front-batched bulk loads: 4x LDG.128 (2 rows x 64 float4)
    const float4* gs = (const float4*)grid_state + (size_t)r0 * (FEAT / 4);
    float4 v[4];
    #pragma unroll
    for (int j = 0; j < 4; j++)
        v[j] = gs[lane + 32 * j];

    // Allow the dependent patch grid to launch early (it only LOADS inputs
    // before its griddepsync; ordering of its stores is still enforced).
    cudaTriggerProgrammaticLaunchCompletion();

    // Lanes 0/1: conf/temp for their row
    if (lane < 2) {
        const int row = r0 + lane;
        const float c  = grid_conf[row];
        const float tm = grid_temp[row];
        *(float2*)(out + (size_t)row * ROW_OUT + FEAT) =
            make_float2(c * DECAY, tm);
    }

    // Row 0 (even): 16B-aligned -> STG.128
    float4* o0 = (float4*)(out + (size_t)r0 * ROW_OUT);
    o0[lane]      = v[0];
    o0[lane + 32] = v[1];

    // Row 1 (odd): 8B-aligned -> 2x STG.64 per float4
    float* o1 = out + (size_t)(r0 + 1) * ROW_OUT;
    #pragma unroll
    for (int j = 2; j < 4; j++) {
        const int q = lane + 32 * (j & 1);
        *(float2*)(o1 + 4 * q)     = make_float2(v[j].x, v[j].y);
        *(float2*)(o1 + 4 * q + 2) = make_float2(v[j].z, v[j].w);
    }
}

// ---------------- Patch kernel: fix up the 64 scattered rows ---------------
// One block per (b, obj). Reads ONLY the original inputs (never `out`), so
// everything up to the griddepsync overlaps smg_copy; only the stores wait.
__global__ __launch_bounds__(64, 1)
void smg_patch(const float* __restrict__ grid_state,
               const float* __restrict__ grid_conf,
               const float* __restrict__ grid_temp,
               const float* __restrict__ obj_feat,
               const float* __restrict__ positions,
               const float* __restrict__ occl,
               float* __restrict__ out)
{
    const int bo = blockIdx.x;                   // 0..63
    const int b  = bo >> 4;
    const int o  = bo & (NOBJ - 1);
    const int t  = threadIdx.x;                  // 0..63 -> one float4 each

    const float px = positions[bo * 2 + 0];
    const float py = positions[bo * 2 + 1];
    const int gwt = (int)fminf(fmaxf(px * (float)(GW - 1), 0.0f), 63.0f);
    const int ght = (int)fminf(fmaxf(py * (float)(GH - 1), 0.0f), 63.0f);
    const int row = (((b * GH + ght) * GW) + gwt) * NOBJ + o;

    const bool vis = occl[bo] < 0.5f;
    const float a  = vis ? 0.8f : 0.3f;
    const float ia = 1.0f - a;

    const float4 g4 = ((const float4*)(grid_state + (size_t)row * FEAT))[t];
    const float4 f4 = ((const float4*)(obj_feat   + (size_t)bo  * FEAT))[t];
    float4 r;
    r.x = a * f4.x + ia * g4.x;
    r.y = a * f4.y + ia * g4.y;
    r.z = a * f4.z + ia * g4.z;
    r.w = a * f4.w + ia * g4.w;

    float c = 0.0f, tm = 0.0f;
    if (t == 0) {
        c  = grid_conf[row];
        tm = grid_temp[row];
        c  = vis ? fminf(1.0f, c * 0.9f + 0.5f) : c * DECAY;
        tm += vis ? 1.0f : 0.5f;
    }

    // Wait for smg_copy to fully complete (WAW ordering on these rows),
    // then overwrite. All loads above already happened in its shadow.
    cudaGridDependencySynchronize();

    float* orow = out + (size_t)row * ROW_OUT;   // 8B-aligned always
    *(float2*)(orow + 4 * t)     = make_float2(r.x, r.y);
    *(float2*)(orow + 4 * t + 2) = make_float2(r.z, r.w);
    if (t == 0)
        *(float2*)(orow + FEAT) = make_float2(c * DECAY, tm);
}

extern "C" void kernel_launch(void* const* d_in, const int* in_sizes, int n_in,
                              void* d_out, int out_size)
{
    const float* grid_state = (const float*)d_in[0];
    const float* grid_conf  = (const float*)d_in[1];
    const float* grid_temp  = (const float*)d_in[2];
    const float* obj_feat   = (const float*)d_in[3];
    const float* positions  = (const float*)d_in[4];
    const float* occl       = (const float*)d_in[5];
    float* out = (float*)d_out;

    smg_copy<<<NROWS / 16, 256>>>(grid_state, grid_conf, grid_temp, out);

    // Patch launch with PDL: may start while smg_copy drains; its stores
    // are ordered by cudaGridDependencySynchronize() in the kernel.
    cudaLaunchConfig_t cfg = {};
    cfg.gridDim  = dim3(BATCH * NOBJ, 1, 1);
    cfg.blockDim = dim3(64, 1, 1);
    cfg.dynamicSmemBytes = 0;
    cfg.stream = 0;  // legacy default stream (same as <<<>>> above)
    cudaLaunchAttribute attr[1];
    attr[0].id = cudaLaunchAttributeProgrammaticStreamSerialization;
    attr[0].val.programmaticStreamSerializationAllowed = 1;
    cfg.attrs = attr;
    cfg.numAttrs = 1;
    cudaLaunchKernelEx(&cfg, smg_patch,
                       grid_state, grid_conf, grid_temp,
                       obj_feat, positions, occl, out);
}